// round 4
// baseline (speedup 1.0000x reference)
#include <cuda_runtime.h>

// BiLinearInteractionLayer: out[b, p, :] = (x[b,i_p,:] @ W) * x[b,j_p,:]
// x: [2048, 40, 64] fp32, W: [64, 64] fp32, out: [2048, 780*64] fp32.
// One CTA (320 threads) per batch row.
// Thread (col = tid&15, fb = tid>>4, fb in 0..19) owns rows {fb, 39-fb}:
//   - nj(fb) + nj(39-fb) = 39: every thread stores exactly 39 float4s.
//   - j-range of row (39-fb) is a subset of row fb's range: ONE j-loop,
//     one LDS.128 of x[j] feeds up to two stores.
// Phase 2 keeps both xw rows in registers (no sxw smem, no a-reloads).

#define F_NUM   40
#define EDIM    64
#define RPAD    68          // floats per sx row -> bank stride 4 mod 32
#define RPAD4   17
#define NPAIR   780
#define TPB     320
#define BATCH_N 2048

__global__ __launch_bounds__(TPB, 5)
void bilinear_interact_kernel(const float* __restrict__ x,
                              const float* __restrict__ w,
                              float* __restrict__ out)
{
    __shared__ float sx[F_NUM * RPAD];    // 10.6 KB
    __shared__ float sw[EDIM * EDIM];     // 16 KB

    const int b   = blockIdx.x;
    const int tid = threadIdx.x;

    // ---- Phase 1: stage inputs ------------------------------------------
    {
        const float4* xg  = reinterpret_cast<const float4*>(x + (size_t)b * F_NUM * EDIM);
        float4*       sx4 = reinterpret_cast<float4*>(sx);
        #pragma unroll
        for (int t = tid; t < F_NUM * EDIM / 4; t += TPB) {
            const int row = t >> 4;
            const int c   = t & 15;
            sx4[row * RPAD4 + c] = xg[t];
        }
        const float4* wg  = reinterpret_cast<const float4*>(w);
        float4*       sw4 = reinterpret_cast<float4*>(sw);
        #pragma unroll
        for (int t = tid; t < EDIM * EDIM / 4; t += TPB) sw4[t] = wg[t];
    }
    __syncthreads();

    const int col = tid & 15;   // float4 column (d/4)
    const int fb  = tid >> 4;   // 0..19
    const int i0  = fb;         // 0..19
    const int i1  = F_NUM - 1 - fb;  // 39..20

    // ---- Phase 2: xw rows i0, i1 -> registers ---------------------------
    float4 acc0 = make_float4(0.f, 0.f, 0.f, 0.f);
    float4 acc1 = acc0;
    {
        const float4* swv = reinterpret_cast<const float4*>(sw);
        #pragma unroll 8
        for (int k = 0; k < EDIM; k++) {
            const float4 wv = swv[k * 16 + col];
            const float a0 = sx[i0 * RPAD + k];
            const float a1 = sx[i1 * RPAD + k];
            acc0.x += a0 * wv.x; acc0.y += a0 * wv.y; acc0.z += a0 * wv.z; acc0.w += a0 * wv.w;
            acc1.x += a1 * wv.x; acc1.y += a1 * wv.y; acc1.z += a1 * wv.z; acc1.w += a1 * wv.w;
        }
    }
    // No sync: phase 3 reads sx (already sync'd) and registers only.

    // ---- Phase 3: merged pair streaming ---------------------------------
    // pb(i) = i*(79-i)/2. For j = fb+1..39:
    //   store (i0, j) always; store (i1, j) when j > i1 (i.e. j >= 40-fb).
    {
        float4*       out4 = reinterpret_cast<float4*>(out + (size_t)b * NPAIR * EDIM);
        const float4* sx4  = reinterpret_cast<const float4*>(sx);

        const int pb0     = (i0 * (2 * F_NUM - 1 - i0)) >> 1;
        const int pb1     = (i1 * (2 * F_NUM - 1 - i1)) >> 1;
        const int jstart1 = i1 + 1;                 // 40 - fb

        float4*       o0 = out4 + (size_t)(pb0 - (fb + 1)) * 16 + col;      // index by j
        float4*       o1 = out4 + (size_t)(pb1 - jstart1) * 16 + col;      // index by j
        const float4* vb = sx4 + col;

        #pragma unroll 4
        for (int j = fb + 1; j < F_NUM; j++) {
            const float4 v = vb[j * RPAD4];
            const float4 r0 = make_float4(acc0.x * v.x, acc0.y * v.y,
                                          acc0.z * v.z, acc0.w * v.w);
            __stcs(o0 + (size_t)j * 16, r0);
            if (j >= jstart1) {
                const float4 r1 = make_float4(acc1.x * v.x, acc1.y * v.y,
                                              acc1.z * v.z, acc1.w * v.w);
                __stcs(o1 + (size_t)j * 16, r1);
            }
        }
    }
}

extern "C" void kernel_launch(void* const* d_in, const int* in_sizes, int n_in,
                              void* d_out, int out_size)
{
    const float* x = (const float*)d_in[0];   // [2048, 40, 64]
    const float* w = (const float*)d_in[1];   // [64, 64]
    float* out = (float*)d_out;               // [2048, 780*64]
    (void)in_sizes; (void)n_in; (void)out_size;

    bilinear_interact_kernel<<<BATCH_N, TPB>>>(x, w, out);
}

// round 5
// speedup vs baseline: 1.0516x; 1.0516x over previous
#include <cuda_runtime.h>

// BiLinearInteractionLayer: out[b, p, :] = (x[b,i_p,:] @ W) * x[b,j_p,:]
// x: [2048, 40, 64] fp32, W: [64, 64] fp32, out: [2048, 780*64] fp32.
//
// One CTA (320 threads) per TWO batch rows: the W smem stream in the GEMM is
// per-warp-per-k regardless of how many accumulators it feeds, so feeding
// 2 rows x 2 batches amortizes the dominant phase-2 LDS cost 2x.
// Thread (col = tid&15, fb = tid>>4, fb in 0..19) owns rows {fb, 39-fb} of
// both batches; nj(fb)+nj(39-fb) = 39 -> every thread stores exactly 39
// float4 per batch. Phase 3 = clean separate loops (no predication).

#define F_NUM   40
#define EDIM    64
#define RPAD    68          // floats per sx row: stride 4 mod 32 banks
#define RPAD4   17
#define NPAIR   780
#define TPB     320
#define NB      2           // batch rows per CTA
#define GRID    1024

__global__ __launch_bounds__(TPB, 4)
void bilinear_interact_kernel(const float* __restrict__ x,
                              const float* __restrict__ w,
                              float* __restrict__ out)
{
    __shared__ float sx[NB * F_NUM * RPAD];   // 21.8 KB (80 padded rows)
    __shared__ float sw[EDIM * EDIM];         // 16 KB

    const int    tid   = threadIdx.x;
    const size_t bbase = (size_t)blockIdx.x * NB;

    // ---- Phase 1: stage 2 batch rows of x (padded) + W -------------------
    {
        const float4* xg  = reinterpret_cast<const float4*>(x + bbase * F_NUM * EDIM);
        float4*       sx4 = reinterpret_cast<float4*>(sx);
        #pragma unroll
        for (int t = tid; t < NB * F_NUM * EDIM / 4; t += TPB) {
            const int row = t >> 4;      // 0..79 (global padded row)
            const int c   = t & 15;
            sx4[row * RPAD4 + c] = xg[t];
        }
        const float4* wg  = reinterpret_cast<const float4*>(w);
        float4*       sw4 = reinterpret_cast<float4*>(sw);
        #pragma unroll
        for (int t = tid; t < EDIM * EDIM / 4; t += TPB) sw4[t] = wg[t];
    }
    __syncthreads();

    const int col = tid & 15;        // float4 column (d/4)
    const int fb  = tid >> 4;        // 0..19
    const int i0  = fb;
    const int i1  = F_NUM - 1 - fb;  // 39..20

    // ---- Phase 2: xw rows {i0,i1} x {batch A,B} -> 4 register accs -------
    float4 aA0 = make_float4(0.f, 0.f, 0.f, 0.f);
    float4 aA1 = aA0, aB0 = aA0, aB1 = aA0;
    {
        const float4* swv = reinterpret_cast<const float4*>(sw);
        const float4* xA0 = reinterpret_cast<const float4*>(sx) + i0 * RPAD4;
        const float4* xA1 = reinterpret_cast<const float4*>(sx) + i1 * RPAD4;
        const float4* xB0 = reinterpret_cast<const float4*>(sx) + (F_NUM + i0) * RPAD4;
        const float4* xB1 = reinterpret_cast<const float4*>(sx) + (F_NUM + i1) * RPAD4;

        #pragma unroll 4
        for (int k4 = 0; k4 < EDIM / 4; k4++) {
            const float4 vA0 = xA0[k4];
            const float4 vA1 = xA1[k4];
            const float4 vB0 = xB0[k4];
            const float4 vB1 = xB1[k4];
            #pragma unroll
            for (int kk = 0; kk < 4; kk++) {
                const float4 wv = swv[(k4 * 4 + kk) * 16 + col];
                const float sA0 = (kk == 0) ? vA0.x : (kk == 1) ? vA0.y : (kk == 2) ? vA0.z : vA0.w;
                const float sA1 = (kk == 0) ? vA1.x : (kk == 1) ? vA1.y : (kk == 2) ? vA1.z : vA1.w;
                const float sB0 = (kk == 0) ? vB0.x : (kk == 1) ? vB0.y : (kk == 2) ? vB0.z : vB0.w;
                const float sB1 = (kk == 0) ? vB1.x : (kk == 1) ? vB1.y : (kk == 2) ? vB1.z : vB1.w;
                aA0.x += sA0 * wv.x; aA0.y += sA0 * wv.y; aA0.z += sA0 * wv.z; aA0.w += sA0 * wv.w;
                aA1.x += sA1 * wv.x; aA1.y += sA1 * wv.y; aA1.z += sA1 * wv.z; aA1.w += sA1 * wv.w;
                aB0.x += sB0 * wv.x; aB0.y += sB0 * wv.y; aB0.z += sB0 * wv.z; aB0.w += sB0 * wv.w;
                aB1.x += sB1 * wv.x; aB1.y += sB1 * wv.y; aB1.z += sB1 * wv.z; aB1.w += sB1 * wv.w;
            }
        }
    }
    // No sync: phase 3 reads sx (sync'd above) and registers only.

    // ---- Phase 3: stream pair products, 2 rows x 2 batches ---------------
    {
        float4*       outA = reinterpret_cast<float4*>(out + bbase * NPAIR * EDIM);
        float4*       outB = outA + (size_t)NPAIR * (EDIM / 4);
        const float4* sA   = reinterpret_cast<const float4*>(sx);
        const float4* sB   = sA + F_NUM * RPAD4;

        const int pb0 = (i0 * (2 * F_NUM - 1 - i0)) >> 1;   // i0*(79-i0)/2
        const int pb1 = (i1 * (2 * F_NUM - 1 - i1)) >> 1;

        // row i0: j = i0+1 .. 39   (39-fb stores)
        {
            float4* oA = outA + (size_t)(pb0 - (i0 + 1)) * 16 + col;
            float4* oB = outB + (size_t)(pb0 - (i0 + 1)) * 16 + col;
            #pragma unroll 4
            for (int j = i0 + 1; j < F_NUM; j++) {
                const float4 vA = sA[j * RPAD4 + col];
                const float4 vB = sB[j * RPAD4 + col];
                __stcs(oA + (size_t)j * 16, make_float4(aA0.x * vA.x, aA0.y * vA.y,
                                                        aA0.z * vA.z, aA0.w * vA.w));
                __stcs(oB + (size_t)j * 16, make_float4(aB0.x * vB.x, aB0.y * vB.y,
                                                        aB0.z * vB.z, aB0.w * vB.w));
            }
        }
        // row i1: j = i1+1 .. 39   (fb stores; empty for fb==0)
        {
            float4* oA = outA + (size_t)(pb1 - (i1 + 1)) * 16 + col;
            float4* oB = outB + (size_t)(pb1 - (i1 + 1)) * 16 + col;
            #pragma unroll 4
            for (int j = i1 + 1; j < F_NUM; j++) {
                const float4 vA = sA[j * RPAD4 + col];
                const float4 vB = sB[j * RPAD4 + col];
                __stcs(oA + (size_t)j * 16, make_float4(aA1.x * vA.x, aA1.y * vA.y,
                                                        aA1.z * vA.z, aA1.w * vA.w));
                __stcs(oB + (size_t)j * 16, make_float4(aB1.x * vB.x, aB1.y * vB.y,
                                                        aB1.z * vB.z, aB1.w * vB.w));
            }
        }
    }
}

extern "C" void kernel_launch(void* const* d_in, const int* in_sizes, int n_in,
                              void* d_out, int out_size)
{
    const float* x = (const float*)d_in[0];   // [2048, 40, 64]
    const float* w = (const float*)d_in[1];   // [64, 64]
    float* out = (float*)d_out;               // [2048, 780*64]
    (void)in_sizes; (void)n_in; (void)out_size;

    bilinear_interact_kernel<<<GRID, TPB>>>(x, w, out);
}